// round 14
// baseline (speedup 1.0000x reference)
#include <cuda_runtime.h>
#include <cuda_fp16.h>
#include <cstdint>

#define BATCH 1024
#define TT 13
#define YY 188
#define HH 512
#define GG 1536
#define DS 13
#define KPAD 192
#define NTH 128
#define SEPIL 100

// ---------------- scratch ----------------
__device__ float  g_xg0[(size_t)TT * BATCH * GG];   // ring: xg0 + b_ih0 (permuted cols)
__device__ float  g_xg1r[2][(size_t)BATCH * GG];    // raw xg1 (+b_ih1), parity by t
__device__ float  g_h0[2][(size_t)BATCH * HH];
__device__ __half g_h0f[2][(size_t)BATCH * HH];
__device__ float  g_h1[2][(size_t)BATCH * HH];
__device__ __half g_h1f[2][(size_t)BATCH * HH];
__device__ float  g_xlast[(size_t)BATCH * YY];
__device__ __half g_xlastf[(size_t)BATCH * KPAD];
__device__ __half g_xpf[(size_t)BATCH * TT * KPAD];
__device__ __half g_Whh0h[(size_t)GG * HH];
__device__ __half g_Wih1h[(size_t)GG * HH];
__device__ __half g_Whh1h[(size_t)GG * HH];
__device__ __half g_Wih0h[(size_t)GG * KPAD];
__device__ __half g_Wouth[(size_t)KPAD * HH];
__device__ float g_bih0p[GG], g_bhh0p[GG], g_bih1p[GG], g_bhh1p[GG];

// ---------------- helpers ----------------
__device__ __forceinline__ void cp16(uint32_t d, const void* s) {
    asm volatile("cp.async.cg.shared.global [%0], [%1], 16;\n" :: "r"(d), "l"(s));
}
__device__ __forceinline__ void cpc()  { asm volatile("cp.async.commit_group;\n"); }
__device__ __forceinline__ void cpw1() { asm volatile("cp.async.wait_group 1;\n"); }
__device__ __forceinline__ void gdwait() {
    asm volatile("griddepcontrol.wait;" ::: "memory");
}
__device__ __forceinline__ void gdlaunch() {
    asm volatile("griddepcontrol.launch_dependents;" ::: "memory");
}
__device__ __forceinline__ float sigm(float x)   { return 1.f / (1.f + __expf(-x)); }
__device__ __forceinline__ float tanhf_(float x) { return 2.f * sigm(2.f * x) - 1.f; }

__device__ __forceinline__ void ldm4(uint32_t* r, uint32_t a) {
    asm volatile("ldmatrix.sync.aligned.m8n8.x4.shared.b16 {%0,%1,%2,%3}, [%4];"
        : "=r"(r[0]), "=r"(r[1]), "=r"(r[2]), "=r"(r[3]) : "r"(a));
}
__device__ __forceinline__ uint32_t relu2(uint32_t v) {
    uint32_t r; asm("max.f16x2 %0, %1, %2;" : "=r"(r) : "r"(v), "r"(0u)); return r;
}
__device__ __forceinline__ void mma16(float* d, const uint32_t* a, uint32_t b0, uint32_t b1) {
    asm volatile("mma.sync.aligned.m16n8k16.row.col.f32.f16.f16.f32 "
        "{%0,%1,%2,%3},{%4,%5,%6,%7},{%8,%9},{%0,%1,%2,%3};"
        : "+f"(d[0]), "+f"(d[1]), "+f"(d[2]), "+f"(d[3])
        : "r"(a[0]), "r"(a[1]), "r"(a[2]), "r"(a[3]), "r"(b0), "r"(b1));
}

// modes
#define M_GATE0 0
#define M_GATE1 1
#define M_STORE 2
#define M_XGALL 4
#define M_OUT   5

// ---- GEMM core: BM=64, BN=96, 4 warps (2x2), BK=64 halves, 3-stage, occ 3 ----
// NTILES consecutive 96-col output tiles per CTA (wave packing).
#define ASTR  8192      // 64*128 bytes per A stage
#define BSTRb 12288     // 96*128 bytes per B stage
#define SMEMB (3 * (ASTR + BSTRb))   // 61440

template<int MODE, int NK, bool ZG, bool RELU_A, int NTILES>
__device__ __forceinline__ void gcore(
    int m0, int n0base,
    const __half* __restrict__ A, int lda,
    const __half* __restrict__ Bw, int ldb,
    const float* __restrict__ biasg,
    const float* __restrict__ gh, const float* __restrict__ bhh,
    const float* __restrict__ hsrc, float* __restrict__ hdst, __half* __restrict__ hdstf,
    float* __restrict__ C, float* __restrict__ dout, int dstep)
{
    extern __shared__ float sm[];
    const uint32_t sAb = (uint32_t)__cvta_generic_to_shared(sm);
    const uint32_t sBb = sAb + 3 * ASTR;

    const int tid = threadIdx.x, lane = tid & 31, warp = tid >> 5;
    const int warpM = warp >> 1, warpN = warp & 1;     // 2 x 2
    const int lane4 = lane >> 2, lq = lane & 3;

    // smem fragment addresses (independent of n0)
    const int subrow = lane & 7;
    uint32_t aBase[2]; int r7A[2];
#pragma unroll
    for (int i = 0; i < 2; i++) {
        int row = warpM * 32 + i * 16 + subrow + ((lane >> 3) & 1) * 8;
        aBase[i] = sAb + row * 128; r7A[i] = row & 7;
    }
    uint32_t bBase[3]; int r7B[3];
#pragma unroll
    for (int jj = 0; jj < 3; jj++) {
        int row = warpN * 48 + jj * 16 + subrow + (lane >> 4) * 8;
        bBase[jj] = sBb + row * 128; r7B[jj] = row & 7;
    }
    const int kvA = lane >> 4;
    const int kvB = (lane >> 3) & 1;

#pragma unroll 1
    for (int tile = 0; tile < NTILES; tile++) {
        const int n0 = n0base + tile * 96;

        float acc[2][6][4];
#pragma unroll
        for (int i = 0; i < 2; i++)
#pragma unroll
            for (int j = 0; j < 6; j++)
#pragma unroll
                for (int q = 0; q < 4; q++) acc[i][j][q] = 0.f;

        auto loadA = [&](int st, int k0) {
#pragma unroll
            for (int v = tid; v < 64 * 8; v += NTH) {
                int r = v >> 3, vc = v & 7;
                cp16(sAb + st * ASTR + r * 128 + ((vc ^ (r & 7)) << 4),
                     A + (size_t)(m0 + r) * lda + k0 + vc * 8);
            }
        };
        auto loadB = [&](int st, int k0) {
#pragma unroll
            for (int v = tid; v < 96 * 8; v += NTH) {
                int r = v >> 3, vc = v & 7;
                cp16(sBb + st * BSTRb + r * 128 + ((vc ^ (r & 7)) << 4),
                     Bw + (size_t)(n0 + r) * ldb + k0 + vc * 8);
            }
        };

        // B (weights) has NO dependency on the predecessor kernel: issue before
        // griddepcontrol.wait (tile 0) so it overlaps the predecessor's drain.
        loadB(0, 0);
        loadB(1, 64);
        loadB(2, 128);
        if (tile == 0) gdwait();        // predecessor results now visible
        loadA(0, 0);  cpc();            // G0 = {B0,B1,B2,A0}
        loadA(1, 64); cpc();            // G1 = {A1}

        uint32_t aF[2][2][4], bF[2][3][4];
        auto ldfr = [&](int st, int ks, int buf) {
#pragma unroll
            for (int i = 0; i < 2; i++) {
                ldm4(aF[buf][i], aBase[i] + st * ASTR + (((2 * ks + kvA) ^ r7A[i]) << 4));
                if (RELU_A) {
#pragma unroll
                    for (int q = 0; q < 4; q++) aF[buf][i][q] = relu2(aF[buf][i][q]);
                }
            }
#pragma unroll
            for (int jj = 0; jj < 3; jj++)
                ldm4(bF[buf][jj], bBase[jj] + st * BSTRb + (((2 * ks + kvB) ^ r7B[jj]) << 4));
        };

        for (int kt = 0; kt < NK; kt++) {
            cpw1();                      // all groups except newest -> stage kt ready
            __syncthreads();
            if (kt + 2 < NK) {
                int st = (kt + 2) % 3, k0 = (kt + 2) * 64;
                if (kt + 2 >= 3) loadB(st, k0);   // stages 0..2 B pre-issued
                loadA(st, k0);
            }
            cpc();                       // unconditional: keeps group<->stage invariant

            const int st = kt % 3;
            ldfr(st, 0, 0);
#pragma unroll
            for (int ks = 0; ks < 4; ks++) {
                const int cur = ks & 1;
                if (ks < 3) ldfr(st, ks + 1, cur ^ 1);
#pragma unroll
                for (int j = 0; j < 6; j++)
#pragma unroll
                    for (int i = 0; i < 2; i++)
                        mma16(acc[i][j], aF[cur][i],
                              bF[cur][j >> 1][(j & 1) * 2], bF[cur][j >> 1][(j & 1) * 2 + 1]);
            }
        }
        __syncthreads();

        // ---------------- epilogues ----------------
        if (MODE == M_STORE || MODE == M_XGALL) {
#pragma unroll
            for (int i = 0; i < 2; i++) {
                int rr = m0 + warpM * 32 + i * 16 + lane4;
#pragma unroll
                for (int j = 0; j < 6; j++) {
                    int cc = n0 + warpN * 48 + j * 8 + lq * 2;
#pragma unroll
                    for (int q = 0; q < 4; q++) {
                        int r2 = rr + (q >> 1) * 8, c2 = cc + (q & 1);
                        float v = acc[i][j][q] + biasg[c2];
                        if (MODE == M_STORE) {
                            C[(size_t)r2 * GG + c2] = v;
                        } else {
                            int b = r2 / TT, t = r2 % TT;
                            C[((size_t)t * BATCH + b) * GG + c2] = v;
                        }
                    }
                }
            }
            if (MODE == M_XGALL) {
                // fold: compute h0[0] (t=0 gate, h_prev=0) for rows with t==0.
                __syncthreads();
#pragma unroll
                for (int i = 0; i < 2; i++) {
                    int rl = warpM * 32 + i * 16 + lane4;
#pragma unroll
                    for (int j = 0; j < 6; j++) {
                        int cl = warpN * 48 + j * 8 + lq * 2;
                        *(float2*)&sm[rl * SEPIL + cl]       = make_float2(acc[i][j][0], acc[i][j][1]);
                        *(float2*)&sm[(rl + 8) * SEPIL + cl] = make_float2(acc[i][j][2], acc[i][j][3]);
                    }
                }
                __syncthreads();
                const int jbase = n0 / 3;
                for (int idx = tid; idx < 64 * 32; idx += NTH) {
                    int bl = idx >> 5, jj = idx & 31;
                    int rr = m0 + bl;
                    if (rr % TT != 0) continue;
                    int b = rr / TT;
                    int cg = n0 + 3 * jj;
                    float xr = sm[bl * SEPIL + 3 * jj + 0] + g_bih0p[cg];
                    float xz = sm[bl * SEPIL + 3 * jj + 1] + g_bih0p[cg + 1];
                    float xn = sm[bl * SEPIL + 3 * jj + 2] + g_bih0p[cg + 2];
                    float r = sigm(xr + g_bhh0p[cg]);
                    float z = sigm(xz + g_bhh0p[cg + 1]);
                    float n = tanhf_(xn + r * g_bhh0p[cg + 2]);
                    float hv = (1.f - z) * n;
                    g_h0[0][(size_t)b * HH + jbase + jj] = hv;
                    g_h0f[0][(size_t)b * HH + jbase + jj] = __float2half_rn(hv);
                }
            }
        } else if (MODE == M_OUT) {
#pragma unroll
            for (int i = 0; i < 2; i++) {
                int rr = m0 + warpM * 32 + i * 16 + lane4;
#pragma unroll
                for (int j = 0; j < 6; j++) {
                    int cc = n0 + warpN * 48 + j * 8 + lq * 2;
#pragma unroll
                    for (int q = 0; q < 4; q++) {
                        int r2 = rr + (q >> 1) * 8, c2 = cc + (q & 1);
                        if (c2 < YY) {
                            float v = acc[i][j][q] + biasg[c2] + g_xlast[(size_t)r2 * YY + c2];
                            dout[((size_t)r2 * DS + dstep) * YY + c2] = v;
                            g_xlast[(size_t)r2 * YY + c2] = v;
                            g_xlastf[(size_t)r2 * KPAD + c2] = __float2half_rn(v);
                        }
                    }
                }
            }
        } else {  // M_GATE0 / M_GATE1: acc -> smem -> fused gate math
#pragma unroll
            for (int i = 0; i < 2; i++) {
                int rl = warpM * 32 + i * 16 + lane4;
#pragma unroll
                for (int j = 0; j < 6; j++) {
                    int cl = warpN * 48 + j * 8 + lq * 2;
                    *(float2*)&sm[rl * SEPIL + cl]       = make_float2(acc[i][j][0], acc[i][j][1]);
                    *(float2*)&sm[(rl + 8) * SEPIL + cl] = make_float2(acc[i][j][2], acc[i][j][3]);
                }
            }
            __syncthreads();
            const int jbase = n0 / 3;
            for (int idx = tid; idx < 64 * 32; idx += NTH) {
                int bl = idx >> 5, jj = idx & 31;
                int b = m0 + bl;
                int cg = n0 + 3 * jj;
                float ar = sm[bl * SEPIL + 3 * jj + 0];
                float az = sm[bl * SEPIL + 3 * jj + 1];
                float an = sm[bl * SEPIL + 3 * jj + 2];
                float xr, xz, xn, gr, gz, gn, hp;
                if (MODE == M_GATE0) {
                    const float* xg = gh + (size_t)b * GG;   // x-side pre-stored WITH bias
                    xr = xg[cg]; xz = xg[cg + 1]; xn = xg[cg + 2];
                    gr = ar + bhh[cg]; gz = az + bhh[cg + 1]; gn = an + bhh[cg + 2];
                    hp = hsrc[(size_t)b * HH + jbase + jj];
                } else {
                    xr = ar + biasg[cg]; xz = az + biasg[cg + 1]; xn = an + biasg[cg + 2];
                    if (ZG) {
                        gr = bhh[cg]; gz = bhh[cg + 1]; gn = bhh[cg + 2]; hp = 0.f;
                    } else {
                        const float* g = gh + (size_t)b * GG;
                        gr = g[cg]; gz = g[cg + 1]; gn = g[cg + 2];
                        hp = hsrc[(size_t)b * HH + jbase + jj];
                    }
                }
                float r = sigm(xr + gr), z = sigm(xz + gz);
                float nn_ = tanhf_(xn + r * gn);
                float hv = (1.f - z) * nn_ + z * hp;
                hdst[(size_t)b * HH + jbase + jj] = hv;
                hdstf[(size_t)b * HH + jbase + jj] = __float2half_rn(hv);
            }
        }
        if (tile + 1 < NTILES) __syncthreads();   // epilogue smem vs next tile's cp.async
    }
}

// ---------------- wavefront phase kernel ----------------
// roles: 0=G0(t=p)  1=X1(t=p-1)  2=G1(t=p-2)  3=XGN (xg0_new, p==1, d>=1)
// grid (8,16,nz): each CTA does 2 consecutive 96-col tiles (one-wave packing).
__global__ void __launch_bounds__(NTH, 3) k_phase(int d, int p) {
    int m0 = blockIdx.y * 64, n0base = blockIdx.x * 192;
    int z = blockIdx.z;
    int role;
    if (p == 1)       role = (z == 0) ? 0 : (z == 1) ? 1 : 3;
    else if (p <= 12) role = z;
    else if (p == 13) role = z + 1;
    else              role = 2;

    if (role == 0) {
        int t = p;
        int slot = (d + t) % TT;
        gcore<M_GATE0, 8, false, false, 2>(m0, n0base,
            g_h0f[(t - 1) & 1], HH, g_Whh0h, HH, nullptr,
            g_xg0 + (size_t)slot * BATCH * GG, g_bhh0p,
            g_h0[(t - 1) & 1], g_h0[t & 1], g_h0f[t & 1],
            nullptr, nullptr, 0);
    } else if (role == 1) {
        int t = p - 1;
        if (t == 0)
            gcore<M_GATE1, 8, true, false, 2>(m0, n0base,
                g_h0f[0], HH, g_Wih1h, HH, g_bih1p,
                nullptr, g_bhh1p,
                nullptr, g_h1[0], g_h1f[0], nullptr, nullptr, 0);
        else
            gcore<M_STORE, 8, false, false, 2>(m0, n0base,
                g_h0f[t & 1], HH, g_Wih1h, HH, g_bih1p,
                nullptr, nullptr, nullptr, nullptr, nullptr,
                g_xg1r[t & 1], nullptr, 0);
    } else if (role == 2) {
        int t = p - 2;
        gcore<M_GATE0, 8, false, false, 2>(m0, n0base,
            g_h1f[(t - 1) & 1], HH, g_Whh1h, HH, nullptr,
            g_xg1r[t & 1], g_bhh1p,
            g_h1[(t - 1) & 1], g_h1[t & 1], g_h1f[t & 1],
            nullptr, nullptr, 0);
    } else {
        int slot = (d + 12) % TT;   // == (d-1) % TT for d >= 1
        gcore<M_STORE, 3, false, false, 2>(m0, n0base,
            g_xlastf, KPAD, g_Wih0h, KPAD, g_bih0p,
            nullptr, nullptr, nullptr, nullptr, nullptr,
            g_xg0 + (size_t)slot * BATCH * GG, nullptr, 0);
    }
    gdlaunch();
}

__global__ void __launch_bounds__(NTH, 3) k_xg0_all() {
    gcore<M_XGALL, 3, false, false, 1>(blockIdx.y * 64, blockIdx.x * 96,
        g_xpf, KPAD, g_Wih0h, KPAD, g_bih0p,
        nullptr, nullptr, nullptr, nullptr, nullptr, g_xg0, nullptr, 0);
}

// grid (16,16,2):
//   z=0, x<2 : output GEMM (+residual+feedback)   [32 CTAs]
//   z=1      : gate0 init for NEXT decode's ring slot [256 CTAs]
__global__ void __launch_bounds__(NTH, 3) k_out(float* __restrict__ dout, int dstep,
                                                const float* __restrict__ bout,
                                                int nextslot) {
    if (blockIdx.z == 1) {
        if (nextslot >= 0) {
            gdwait();
            const float* ring = g_xg0 + (size_t)nextslot * BATCH * GG;
            int base = (blockIdx.y * gridDim.x + blockIdx.x) * NTH + threadIdx.x;
            int stride = gridDim.x * gridDim.y * NTH;
            for (int idx = base; idx < BATCH * HH; idx += stride) {
                int b = idx >> 9, j = idx & 511;
                const float* xg = ring + (size_t)b * GG;
                int c = 3 * j;
                float r = sigm(xg[c] + g_bhh0p[c]);
                float z = sigm(xg[c + 1] + g_bhh0p[c + 1]);
                float n = tanhf_(xg[c + 2] + r * g_bhh0p[c + 2]);
                float hv = (1.f - z) * n;
                g_h0[0][idx] = hv;
                g_h0f[0][idx] = __float2half_rn(hv);
            }
        }
        gdlaunch();
        return;
    }
    if (blockIdx.x < 2) {
        gcore<M_OUT, 8, false, true, 1>(blockIdx.y * 64, blockIdx.x * 96,
            g_h1f[0], HH, g_Wouth, HH, bout, nullptr, nullptr,
            nullptr, nullptr, nullptr, nullptr, dout, dstep);
    }
    gdlaunch();
}

__global__ void k_init(const float* __restrict__ x) {
    int idx = blockIdx.x * blockDim.x + threadIdx.x;
    if (idx < BATCH * TT * KPAD) {
        int row = idx / KPAD, k = idx % KPAD;
        g_xpf[idx] = (k < YY) ? __float2half_rn(x[(size_t)row * YY + k]) : __float2half_rn(0.f);
    }
    if (idx < BATCH * KPAD) {
        int b = idx / KPAD, k = idx % KPAD;
        if (k < YY) {
            float v = x[((size_t)b * TT + (TT - 1)) * YY + k];
            g_xlast[(size_t)b * YY + k] = v;
            g_xlastf[idx] = __float2half_rn(v);
        } else {
            g_xlastf[idx] = __float2half_rn(0.f);
        }
    }
}

__global__ void k_prep(const float* __restrict__ Wih0, const float* __restrict__ Whh0,
                       const float* __restrict__ bih0, const float* __restrict__ bhh0,
                       const float* __restrict__ Wih1, const float* __restrict__ Whh1,
                       const float* __restrict__ bih1, const float* __restrict__ bhh1,
                       const float* __restrict__ Wout) {
    int i = blockIdx.x * blockDim.x + threadIdx.x;
    if (i < GG * HH) {
        int c = i / HH, k = i % HH;
        int pr = (c % 3) * HH + c / 3;
        g_Whh0h[i] = __float2half_rn(Whh0[(size_t)pr * HH + k]);
        g_Wih1h[i] = __float2half_rn(Wih1[(size_t)pr * HH + k]);
        g_Whh1h[i] = __float2half_rn(Whh1[(size_t)pr * HH + k]);
    }
    if (i < GG * KPAD) {
        int c = i / KPAD, k = i % KPAD;
        int pr = (c % 3) * HH + c / 3;
        g_Wih0h[i] = (k < YY) ? __float2half_rn(Wih0[(size_t)pr * YY + k]) : __float2half_rn(0.f);
    }
    if (i < KPAD * HH) {
        int r = i / HH, k = i % HH;
        g_Wouth[i] = (r < YY) ? __float2half_rn(Wout[(size_t)r * HH + k]) : __float2half_rn(0.f);
    }
    if (i < GG) {
        int pr = (i % 3) * HH + i / 3;
        g_bih0p[i] = bih0[pr];
        g_bhh0p[i] = bhh0[pr];
        g_bih1p[i] = bih1[pr];
        g_bhh1p[i] = bhh1[pr];
    }
}

// ---------------- host ----------------
static void launch_pdl(const void* func, dim3 grid, dim3 block, size_t smem, void** args) {
    cudaLaunchConfig_t cfg = {};
    cfg.gridDim = grid;
    cfg.blockDim = block;
    cfg.dynamicSmemBytes = smem;
    cudaLaunchAttribute attr[1];
    attr[0].id = cudaLaunchAttributeProgrammaticStreamSerialization;
    attr[0].val.programmaticStreamSerializationAllowed = 1;
    cfg.attrs = attr;
    cfg.numAttrs = 1;
    cfg.stream = 0;
    cudaLaunchKernelExC(&cfg, func, args);
}

extern "C" void kernel_launch(void* const* d_in, const int* in_sizes, int n_in,
                              void* d_out, int out_size) {
    (void)in_sizes; (void)n_in; (void)out_size;
    const float* x    = (const float*)d_in[0];
    const float* Wih0 = (const float*)d_in[1];
    const float* Whh0 = (const float*)d_in[2];
    const float* bih0 = (const float*)d_in[3];
    const float* bhh0 = (const float*)d_in[4];
    const float* Wih1 = (const float*)d_in[5];
    const float* Whh1 = (const float*)d_in[6];
    const float* bih1 = (const float*)d_in[7];
    const float* bhh1 = (const float*)d_in[8];
    const float* Wout = (const float*)d_in[9];
    const float* bout = (const float*)d_in[10];
    float* dout = (float*)d_out;

    cudaFuncSetAttribute(k_phase,   cudaFuncAttributeMaxDynamicSharedMemorySize, SMEMB);
    cudaFuncSetAttribute(k_xg0_all, cudaFuncAttributeMaxDynamicSharedMemorySize, SMEMB);
    cudaFuncSetAttribute(k_out,     cudaFuncAttributeMaxDynamicSharedMemorySize, SMEMB);

    k_prep<<<(GG * HH + 255) / 256, 256>>>(Wih0, Whh0, bih0, bhh0,
                                           Wih1, Whh1, bih1, bhh1, Wout);
    k_init<<<(BATCH * TT * KPAD + 255) / 256, 256>>>(x);
    k_xg0_all<<<dim3(16, BATCH * TT / 64), NTH, SMEMB>>>();   // also seeds h0[0] (t=0 gate)

    for (int d = 0; d < DS; d++) {
        for (int p = 1; p <= 14; p++) {
            int nz;
            if (p == 1)       nz = (d > 0) ? 3 : 2;
            else if (p == 2)  nz = 2;
            else if (p <= 12) nz = 3;
            else if (p == 13) nz = 2;
            else              nz = 1;
            void* args[] = { &d, &p };
            launch_pdl((const void*)&k_phase, dim3(8, 16, nz), dim3(NTH), SMEMB, args);
        }
        {
            int nextslot = (d + 1 < DS) ? (d + 1) % TT : -1;
            void* args[] = { &dout, &d, &bout, &nextslot };
            launch_pdl((const void*)&k_out, dim3(16, 16, 2), dim3(NTH), SMEMB, args);
        }
    }
}

// round 16
// speedup vs baseline: 1.1131x; 1.1131x over previous
#include <cuda_runtime.h>
#include <cuda_fp16.h>
#include <cstdint>

#define BATCH 1024
#define TT 13
#define YY 188
#define HH 512
#define GG 1536
#define DS 13
#define KPAD 192
#define NTH 128
#define SEPIL 100

// ---------------- scratch ----------------
__device__ float  g_xg0[(size_t)TT * BATCH * GG];   // ring: xg0 + b_ih0 (permuted cols)
__device__ float  g_xg1r[2][(size_t)BATCH * GG];    // raw xg1 (+b_ih1), parity by t
__device__ float  g_h0[2][(size_t)BATCH * HH];
__device__ __half g_h0f[2][(size_t)BATCH * HH];
__device__ float  g_h1[3][(size_t)BATCH * HH];      // [2] dedicated to t=0
__device__ __half g_h1f[3][(size_t)BATCH * HH];
__device__ float  g_xlast[(size_t)BATCH * YY];
__device__ __half g_xlastf[(size_t)BATCH * KPAD];
__device__ __half g_xpf[(size_t)BATCH * TT * KPAD];
__device__ __half g_Whh0h[(size_t)GG * HH];
__device__ __half g_Wih1h[(size_t)GG * HH];
__device__ __half g_Whh1h[(size_t)GG * HH];
__device__ __half g_Wih0h[(size_t)GG * KPAD];
__device__ __half g_Wouth[(size_t)KPAD * HH];
__device__ float g_bih0p[GG], g_bhh0p[GG], g_bih1p[GG], g_bhh1p[GG];

// ---------------- helpers ----------------
__device__ __forceinline__ void cp16(uint32_t d, const void* s) {
    asm volatile("cp.async.cg.shared.global [%0], [%1], 16;\n" :: "r"(d), "l"(s));
}
__device__ __forceinline__ void cpc()  { asm volatile("cp.async.commit_group;\n"); }
__device__ __forceinline__ void cpw1() { asm volatile("cp.async.wait_group 1;\n"); }
__device__ __forceinline__ void gdwait() {
    asm volatile("griddepcontrol.wait;" ::: "memory");
}
__device__ __forceinline__ void gdlaunch() {
    asm volatile("griddepcontrol.launch_dependents;" ::: "memory");
}
__device__ __forceinline__ float sigm(float x)   { return 1.f / (1.f + __expf(-x)); }
__device__ __forceinline__ float tanhf_(float x) { return 2.f * sigm(2.f * x) - 1.f; }

__device__ __forceinline__ void ldm4(uint32_t* r, uint32_t a) {
    asm volatile("ldmatrix.sync.aligned.m8n8.x4.shared.b16 {%0,%1,%2,%3}, [%4];"
        : "=r"(r[0]), "=r"(r[1]), "=r"(r[2]), "=r"(r[3]) : "r"(a));
}
__device__ __forceinline__ uint32_t relu2(uint32_t v) {
    uint32_t r; asm("max.f16x2 %0, %1, %2;" : "=r"(r) : "r"(v), "r"(0u)); return r;
}
__device__ __forceinline__ void mma16(float* d, const uint32_t* a, uint32_t b0, uint32_t b1) {
    asm volatile("mma.sync.aligned.m16n8k16.row.col.f32.f16.f16.f32 "
        "{%0,%1,%2,%3},{%4,%5,%6,%7},{%8,%9},{%0,%1,%2,%3};"
        : "+f"(d[0]), "+f"(d[1]), "+f"(d[2]), "+f"(d[3])
        : "r"(a[0]), "r"(a[1]), "r"(a[2]), "r"(a[3]), "r"(b0), "r"(b1));
}

// modes
#define M_GATE0 0
#define M_GATE1 1
#define M_STORE 2
#define M_XGALL 4
#define M_OUT   5

// ---- GEMM core: BM=64, BN=96, 4 warps (2x2), BK=64 halves, 3-stage, occ 3 ----
#define ASTR  8192      // 64*128 bytes per A stage
#define BSTRb 12288     // 96*128 bytes per B stage
#define SMEMB (3 * (ASTR + BSTRb))   // 61440

template<int MODE, int NK, bool ZG, bool RELU_A>
__device__ __forceinline__ void gcore(
    int m0, int n0,
    const __half* __restrict__ A, int lda,
    const __half* __restrict__ Bw, int ldb,
    const float* __restrict__ biasg,
    const float* __restrict__ gh, const float* __restrict__ bhh,
    const float* __restrict__ hsrc, float* __restrict__ hdst, __half* __restrict__ hdstf,
    float* __restrict__ C, float* __restrict__ dout, int dstep)
{
    extern __shared__ float sm[];
    const uint32_t sAb = (uint32_t)__cvta_generic_to_shared(sm);
    const uint32_t sBb = sAb + 3 * ASTR;

    const int tid = threadIdx.x, lane = tid & 31, warp = tid >> 5;
    const int warpM = warp >> 1, warpN = warp & 1;     // 2 x 2
    const int lane4 = lane >> 2, lq = lane & 3;

    float acc[2][6][4];
#pragma unroll
    for (int i = 0; i < 2; i++)
#pragma unroll
        for (int j = 0; j < 6; j++)
#pragma unroll
            for (int q = 0; q < 4; q++) acc[i][j][q] = 0.f;

    auto loadA = [&](int st, int k0) {
#pragma unroll
        for (int v = tid; v < 64 * 8; v += NTH) {
            int r = v >> 3, vc = v & 7;
            cp16(sAb + st * ASTR + r * 128 + ((vc ^ (r & 7)) << 4),
                 A + (size_t)(m0 + r) * lda + k0 + vc * 8);
        }
    };
    auto loadB = [&](int st, int k0) {
#pragma unroll
        for (int v = tid; v < 96 * 8; v += NTH) {
            int r = v >> 3, vc = v & 7;
            cp16(sBb + st * BSTRb + r * 128 + ((vc ^ (r & 7)) << 4),
                 Bw + (size_t)(n0 + r) * ldb + k0 + vc * 8);
        }
    };

    // B (weights) for stages 0..2 has NO dependency on the predecessor kernel:
    // issue before griddepcontrol.wait so it overlaps the predecessor's drain.
    loadB(0, 0);
    loadB(1, 64);
    loadB(2, 128);
    gdwait();                       // predecessor results now visible
    loadA(0, 0);  cpc();            // G0 = {B0,B1,B2,A0}
    loadA(1, 64); cpc();            // G1 = {A1}

    const int subrow = lane & 7;
    uint32_t aBase[2]; int r7A[2];
#pragma unroll
    for (int i = 0; i < 2; i++) {
        int row = warpM * 32 + i * 16 + subrow + ((lane >> 3) & 1) * 8;
        aBase[i] = sAb + row * 128; r7A[i] = row & 7;
    }
    uint32_t bBase[3]; int r7B[3];
#pragma unroll
    for (int jj = 0; jj < 3; jj++) {
        int row = warpN * 48 + jj * 16 + subrow + (lane >> 4) * 8;
        bBase[jj] = sBb + row * 128; r7B[jj] = row & 7;
    }
    const int kvA = lane >> 4;
    const int kvB = (lane >> 3) & 1;

    uint32_t aF[2][2][4], bF[2][3][4];
    auto ldfr = [&](int st, int ks, int buf) {
#pragma unroll
        for (int i = 0; i < 2; i++) {
            ldm4(aF[buf][i], aBase[i] + st * ASTR + (((2 * ks + kvA) ^ r7A[i]) << 4));
            if (RELU_A) {
#pragma unroll
                for (int q = 0; q < 4; q++) aF[buf][i][q] = relu2(aF[buf][i][q]);
            }
        }
#pragma unroll
        for (int jj = 0; jj < 3; jj++)
            ldm4(bF[buf][jj], bBase[jj] + st * BSTRb + (((2 * ks + kvB) ^ r7B[jj]) << 4));
    };

    for (int kt = 0; kt < NK; kt++) {
        cpw1();                      // all groups except newest complete -> stage kt ready
        __syncthreads();
        if (kt + 2 < NK) {
            int st = (kt + 2) % 3, k0 = (kt + 2) * 64;
            if (kt + 2 >= 3) loadB(st, k0);   // stages 0..2 B pre-issued
            loadA(st, k0);
        }
        cpc();                       // unconditional: keeps group<->stage invariant

        const int st = kt % 3;
        ldfr(st, 0, 0);
#pragma unroll
        for (int ks = 0; ks < 4; ks++) {
            const int cur = ks & 1;
            if (ks < 3) ldfr(st, ks + 1, cur ^ 1);
#pragma unroll
            for (int j = 0; j < 6; j++)
#pragma unroll
                for (int i = 0; i < 2; i++)
                    mma16(acc[i][j], aF[cur][i],
                          bF[cur][j >> 1][(j & 1) * 2], bF[cur][j >> 1][(j & 1) * 2 + 1]);
        }
    }
    __syncthreads();

    // ---------------- epilogues ----------------
    if (MODE == M_STORE || MODE == M_XGALL) {
#pragma unroll
        for (int i = 0; i < 2; i++) {
            int rr = m0 + warpM * 32 + i * 16 + lane4;
#pragma unroll
            for (int j = 0; j < 6; j++) {
                int cc = n0 + warpN * 48 + j * 8 + lq * 2;
#pragma unroll
                for (int q = 0; q < 4; q++) {
                    int r2 = rr + (q >> 1) * 8, c2 = cc + (q & 1);
                    float v = acc[i][j][q] + biasg[c2];
                    if (MODE == M_STORE) {
                        C[(size_t)r2 * GG + c2] = v;
                    } else {
                        int b = r2 / TT, t = r2 % TT;
                        C[((size_t)t * BATCH + b) * GG + c2] = v;
                    }
                }
            }
        }
        if (MODE == M_XGALL) {
            // fold: compute h0[0] (t=0 gate, h_prev=0) for rows with t==0.
            __syncthreads();
#pragma unroll
            for (int i = 0; i < 2; i++) {
                int rl = warpM * 32 + i * 16 + lane4;
#pragma unroll
                for (int j = 0; j < 6; j++) {
                    int cl = warpN * 48 + j * 8 + lq * 2;
                    *(float2*)&sm[rl * SEPIL + cl]       = make_float2(acc[i][j][0], acc[i][j][1]);
                    *(float2*)&sm[(rl + 8) * SEPIL + cl] = make_float2(acc[i][j][2], acc[i][j][3]);
                }
            }
            __syncthreads();
            const int jbase = n0 / 3;
            for (int idx = tid; idx < 64 * 32; idx += NTH) {
                int bl = idx >> 5, jj = idx & 31;
                int rr = m0 + bl;
                if (rr % TT != 0) continue;
                int b = rr / TT;
                int cg = n0 + 3 * jj;
                float xr = sm[bl * SEPIL + 3 * jj + 0] + g_bih0p[cg];
                float xz = sm[bl * SEPIL + 3 * jj + 1] + g_bih0p[cg + 1];
                float xn = sm[bl * SEPIL + 3 * jj + 2] + g_bih0p[cg + 2];
                float r = sigm(xr + g_bhh0p[cg]);
                float z = sigm(xz + g_bhh0p[cg + 1]);
                float n = tanhf_(xn + r * g_bhh0p[cg + 2]);
                float hv = (1.f - z) * n;
                g_h0[0][(size_t)b * HH + jbase + jj] = hv;
                g_h0f[0][(size_t)b * HH + jbase + jj] = __float2half_rn(hv);
            }
        }
    } else if (MODE == M_OUT) {
#pragma unroll
        for (int i = 0; i < 2; i++) {
            int rr = m0 + warpM * 32 + i * 16 + lane4;
#pragma unroll
            for (int j = 0; j < 6; j++) {
                int cc = n0 + warpN * 48 + j * 8 + lq * 2;
#pragma unroll
                for (int q = 0; q < 4; q++) {
                    int r2 = rr + (q >> 1) * 8, c2 = cc + (q & 1);
                    if (c2 < YY) {
                        float v = acc[i][j][q] + biasg[c2] + g_xlast[(size_t)r2 * YY + c2];
                        dout[((size_t)r2 * DS + dstep) * YY + c2] = v;
                        g_xlast[(size_t)r2 * YY + c2] = v;
                        g_xlastf[(size_t)r2 * KPAD + c2] = __float2half_rn(v);
                    }
                }
            }
        }
    } else {  // M_GATE0 / M_GATE1: acc -> smem -> fused gate math
#pragma unroll
        for (int i = 0; i < 2; i++) {
            int rl = warpM * 32 + i * 16 + lane4;
#pragma unroll
            for (int j = 0; j < 6; j++) {
                int cl = warpN * 48 + j * 8 + lq * 2;
                *(float2*)&sm[rl * SEPIL + cl]       = make_float2(acc[i][j][0], acc[i][j][1]);
                *(float2*)&sm[(rl + 8) * SEPIL + cl] = make_float2(acc[i][j][2], acc[i][j][3]);
            }
        }
        __syncthreads();
        const int jbase = n0 / 3;
        for (int idx = tid; idx < 64 * 32; idx += NTH) {
            int bl = idx >> 5, jj = idx & 31;
            int b = m0 + bl;
            int cg = n0 + 3 * jj;
            float ar = sm[bl * SEPIL + 3 * jj + 0];
            float az = sm[bl * SEPIL + 3 * jj + 1];
            float an = sm[bl * SEPIL + 3 * jj + 2];
            float xr, xz, xn, gr, gz, gn, hp;
            if (MODE == M_GATE0) {
                const float* xg = gh + (size_t)b * GG;   // x-side pre-stored WITH bias
                xr = xg[cg]; xz = xg[cg + 1]; xn = xg[cg + 2];
                gr = ar + bhh[cg]; gz = az + bhh[cg + 1]; gn = an + bhh[cg + 2];
                hp = hsrc[(size_t)b * HH + jbase + jj];
            } else {
                xr = ar + biasg[cg]; xz = az + biasg[cg + 1]; xn = an + biasg[cg + 2];
                if (ZG) {
                    gr = bhh[cg]; gz = bhh[cg + 1]; gn = bhh[cg + 2]; hp = 0.f;
                } else {
                    const float* g = gh + (size_t)b * GG;
                    gr = g[cg]; gz = g[cg + 1]; gn = g[cg + 2];
                    hp = hsrc[(size_t)b * HH + jbase + jj];
                }
            }
            float r = sigm(xr + gr), z = sigm(xz + gz);
            float nn_ = tanhf_(xn + r * gn);
            float hv = (1.f - z) * nn_ + z * hp;
            hdst[(size_t)b * HH + jbase + jj] = hv;
            hdstf[(size_t)b * HH + jbase + jj] = __float2half_rn(hv);
        }
    }
}

// h1 buffer index: t=0 lives in dedicated buffer 2 (avoids parity alias with t=12)
__device__ __forceinline__ int h1idx(int t) { return (t == 0) ? 2 : (t & 1); }

// ---------------- wavefront phase kernel ----------------
// roles: 0=G0(t=p)  1=X1(t=p-1)  2=G1(t=p-2)  3=XGN(xg0_new)
//        4=OUT(dstep=d-1)  5=GATE0INIT(decode d+1)
// per-p z->role: p=1:{0,1,4(d>0)}  p=2:{0,1,3(d>0)}  p=3..12:{0,1,2}
//                p=13:{1,2}  p=14:{2,5(d<12)}
__global__ void __launch_bounds__(NTH, 3) k_phase(int d, int p,
                                                  float* __restrict__ dout,
                                                  const float* __restrict__ bout) {
    int m0 = blockIdx.y * 64, n0 = blockIdx.x * 96;
    int z = blockIdx.z;
    int role;
    if (p == 1)       role = (z == 2) ? 4 : z;
    else if (p == 2)  role = (z == 2) ? 3 : z;
    else if (p <= 12) role = z;
    else if (p == 13) role = z + 1;
    else              role = (z == 0) ? 2 : 5;

    if (role == 0) {
        int t = p;
        int slot = (d + t) % TT;
        gcore<M_GATE0, 8, false, false>(m0, n0,
            g_h0f[(t - 1) & 1], HH, g_Whh0h, HH, nullptr,
            g_xg0 + (size_t)slot * BATCH * GG, g_bhh0p,
            g_h0[(t - 1) & 1], g_h0[t & 1], g_h0f[t & 1],
            nullptr, nullptr, 0);
    } else if (role == 1) {
        int t = p - 1;
        if (t == 0)
            gcore<M_GATE1, 8, true, false>(m0, n0,
                g_h0f[0], HH, g_Wih1h, HH, g_bih1p,
                nullptr, g_bhh1p,
                nullptr, g_h1[2], g_h1f[2], nullptr, nullptr, 0);
        else
            gcore<M_STORE, 8, false, false>(m0, n0,
                g_h0f[t & 1], HH, g_Wih1h, HH, g_bih1p,
                nullptr, nullptr, nullptr, nullptr, nullptr,
                g_xg1r[t & 1], nullptr, 0);
    } else if (role == 2) {
        int t = p - 2;
        int pidx = h1idx(t - 1);
        gcore<M_GATE0, 8, false, false>(m0, n0,
            g_h1f[pidx], HH, g_Whh1h, HH, nullptr,
            g_xg1r[t & 1], g_bhh1p,
            g_h1[pidx], g_h1[t & 1], g_h1f[t & 1],
            nullptr, nullptr, 0);
    } else if (role == 3) {
        int slot = (d + 12) % TT;   // == (d-1) % TT for d >= 1
        gcore<M_STORE, 3, false, false>(m0, n0,
            g_xlastf, KPAD, g_Wih0h, KPAD, g_bih0p,
            nullptr, nullptr, nullptr, nullptr, nullptr,
            g_xg0 + (size_t)slot * BATCH * GG, nullptr, 0);
    } else if (role == 4) {
        if (blockIdx.x < 2)
            gcore<M_OUT, 8, false, true>(m0, n0,
                g_h1f[0], HH, g_Wouth, HH, bout, nullptr, nullptr,
                nullptr, nullptr, nullptr, nullptr, dout, d - 1);
    } else {  // role 5: gate0 init for decode d+1 (h_prev = 0)
        gdwait();
        const float* ring = g_xg0 + (size_t)((d + 1) % TT) * BATCH * GG;
        int base = (blockIdx.y * gridDim.x + blockIdx.x) * NTH + threadIdx.x;
        int stride = gridDim.x * gridDim.y * NTH;
        for (int idx = base; idx < BATCH * HH; idx += stride) {
            int b = idx >> 9, j = idx & 511;
            const float* xg = ring + (size_t)b * GG;
            int c = 3 * j;
            float r = sigm(xg[c] + g_bhh0p[c]);
            float zz = sigm(xg[c + 1] + g_bhh0p[c + 1]);
            float n = tanhf_(xg[c + 2] + r * g_bhh0p[c + 2]);
            float hv = (1.f - zz) * n;
            g_h0[0][idx] = hv;
            g_h0f[0][idx] = __float2half_rn(hv);
        }
    }
    gdlaunch();
}

// final output GEMM for dstep = 12 (grid (2,16))
__global__ void __launch_bounds__(NTH, 3) k_fout(float* __restrict__ dout,
                                                 const float* __restrict__ bout) {
    gcore<M_OUT, 8, false, true>(blockIdx.y * 64, blockIdx.x * 96,
        g_h1f[0], HH, g_Wouth, HH, bout, nullptr, nullptr,
        nullptr, nullptr, nullptr, nullptr, dout, DS - 1);
    gdlaunch();
}

__global__ void __launch_bounds__(NTH, 3) k_xg0_all() {
    gcore<M_XGALL, 3, false, false>(blockIdx.y * 64, blockIdx.x * 96,
        g_xpf, KPAD, g_Wih0h, KPAD, g_bih0p,
        nullptr, nullptr, nullptr, nullptr, nullptr, g_xg0, nullptr, 0);
}

__global__ void k_init(const float* __restrict__ x) {
    int idx = blockIdx.x * blockDim.x + threadIdx.x;
    if (idx < BATCH * TT * KPAD) {
        int row = idx / KPAD, k = idx % KPAD;
        g_xpf[idx] = (k < YY) ? __float2half_rn(x[(size_t)row * YY + k]) : __float2half_rn(0.f);
    }
    if (idx < BATCH * KPAD) {
        int b = idx / KPAD, k = idx % KPAD;
        if (k < YY) {
            float v = x[((size_t)b * TT + (TT - 1)) * YY + k];
            g_xlast[(size_t)b * YY + k] = v;
            g_xlastf[idx] = __float2half_rn(v);
        } else {
            g_xlastf[idx] = __float2half_rn(0.f);
        }
    }
}

__global__ void k_prep(const float* __restrict__ Wih0, const float* __restrict__ Whh0,
                       const float* __restrict__ bih0, const float* __restrict__ bhh0,
                       const float* __restrict__ Wih1, const float* __restrict__ Whh1,
                       const float* __restrict__ bih1, const float* __restrict__ bhh1,
                       const float* __restrict__ Wout) {
    int i = blockIdx.x * blockDim.x + threadIdx.x;
    if (i < GG * HH) {
        int c = i / HH, k = i % HH;
        int pr = (c % 3) * HH + c / 3;
        g_Whh0h[i] = __float2half_rn(Whh0[(size_t)pr * HH + k]);
        g_Wih1h[i] = __float2half_rn(Wih1[(size_t)pr * HH + k]);
        g_Whh1h[i] = __float2half_rn(Whh1[(size_t)pr * HH + k]);
    }
    if (i < GG * KPAD) {
        int c = i / KPAD, k = i % KPAD;
        int pr = (c % 3) * HH + c / 3;
        g_Wih0h[i] = (k < YY) ? __float2half_rn(Wih0[(size_t)pr * YY + k]) : __float2half_rn(0.f);
    }
    if (i < KPAD * HH) {
        int r = i / HH, k = i % HH;
        g_Wouth[i] = (r < YY) ? __float2half_rn(Wout[(size_t)r * HH + k]) : __float2half_rn(0.f);
    }
    if (i < GG) {
        int pr = (i % 3) * HH + i / 3;
        g_bih0p[i] = bih0[pr];
        g_bhh0p[i] = bhh0[pr];
        g_bih1p[i] = bih1[pr];
        g_bhh1p[i] = bhh1[pr];
    }
}

// ---------------- host ----------------
static void launch_pdl(const void* func, dim3 grid, dim3 block, size_t smem, void** args) {
    cudaLaunchConfig_t cfg = {};
    cfg.gridDim = grid;
    cfg.blockDim = block;
    cfg.dynamicSmemBytes = smem;
    cudaLaunchAttribute attr[1];
    attr[0].id = cudaLaunchAttributeProgrammaticStreamSerialization;
    attr[0].val.programmaticStreamSerializationAllowed = 1;
    cfg.attrs = attr;
    cfg.numAttrs = 1;
    cfg.stream = 0;
    cudaLaunchKernelExC(&cfg, func, args);
}

extern "C" void kernel_launch(void* const* d_in, const int* in_sizes, int n_in,
                              void* d_out, int out_size) {
    (void)in_sizes; (void)n_in; (void)out_size;
    const float* x    = (const float*)d_in[0];
    const float* Wih0 = (const float*)d_in[1];
    const float* Whh0 = (const float*)d_in[2];
    const float* bih0 = (const float*)d_in[3];
    const float* bhh0 = (const float*)d_in[4];
    const float* Wih1 = (const float*)d_in[5];
    const float* Whh1 = (const float*)d_in[6];
    const float* bih1 = (const float*)d_in[7];
    const float* bhh1 = (const float*)d_in[8];
    const float* Wout = (const float*)d_in[9];
    const float* bout = (const float*)d_in[10];
    float* dout = (float*)d_out;

    cudaFuncSetAttribute(k_phase,   cudaFuncAttributeMaxDynamicSharedMemorySize, SMEMB);
    cudaFuncSetAttribute(k_fout,    cudaFuncAttributeMaxDynamicSharedMemorySize, SMEMB);
    cudaFuncSetAttribute(k_xg0_all, cudaFuncAttributeMaxDynamicSharedMemorySize, SMEMB);

    k_prep<<<(GG * HH + 255) / 256, 256>>>(Wih0, Whh0, bih0, bhh0,
                                           Wih1, Whh1, bih1, bhh1, Wout);
    k_init<<<(BATCH * TT * KPAD + 255) / 256, 256>>>(x);
    k_xg0_all<<<dim3(16, BATCH * TT / 64), NTH, SMEMB>>>();   // also seeds h0[0] (t=0 gate)

    for (int d = 0; d < DS; d++) {
        for (int p = 1; p <= 14; p++) {
            int nz;
            if (p == 1)       nz = (d > 0) ? 3 : 2;
            else if (p == 2)  nz = (d > 0) ? 3 : 2;
            else if (p <= 12) nz = 3;
            else if (p == 13) nz = 2;
            else              nz = (d + 1 < DS) ? 2 : 1;
            void* args[] = { &d, &p, &dout, &bout };
            launch_pdl((const void*)&k_phase, dim3(16, 16, nz), dim3(NTH), SMEMB, args);
        }
    }
    {
        void* args[] = { &dout, &bout };
        launch_pdl((const void*)&k_fout, dim3(2, 16), dim3(NTH), SMEMB, args);
    }
}

// round 17
// speedup vs baseline: 1.3593x; 1.2211x over previous
#include <cuda_runtime.h>
#include <cuda_fp16.h>
#include <cstdint>

#define BATCH 1024
#define TT 13
#define YY 188
#define HH 512
#define GG 1536
#define DS 13
#define KPAD 192
#define NTH 256
#define SEPIL 100

// ---------------- scratch ----------------
__device__ float  g_xg0[(size_t)TT * BATCH * GG];   // ring: xg0 + b_ih0 (permuted cols)
__device__ float  g_xg1r[2][(size_t)BATCH * GG];    // raw xg1 (+b_ih1), parity by t
__device__ float  g_h0[2][(size_t)BATCH * HH];
__device__ __half g_h0f[2][(size_t)BATCH * HH];
__device__ float  g_h1[3][(size_t)BATCH * HH];      // [2] dedicated to t=0
__device__ __half g_h1f[3][(size_t)BATCH * HH];
__device__ float  g_xlast[(size_t)BATCH * YY];
__device__ __half g_xlastf[(size_t)BATCH * KPAD];
__device__ __half g_xpf[(size_t)BATCH * TT * KPAD];
__device__ __half g_Whh0h[(size_t)GG * HH];
__device__ __half g_Wih1h[(size_t)GG * HH];
__device__ __half g_Whh1h[(size_t)GG * HH];
__device__ __half g_Wih0h[(size_t)GG * KPAD];
__device__ __half g_Wouth[(size_t)KPAD * HH];
__device__ float g_bih0p[GG], g_bhh0p[GG], g_bih1p[GG], g_bhh1p[GG];

// ---------------- helpers ----------------
__device__ __forceinline__ void cp16(uint32_t d, const void* s) {
    asm volatile("cp.async.cg.shared.global [%0], [%1], 16;\n" :: "r"(d), "l"(s));
}
__device__ __forceinline__ void cpc()  { asm volatile("cp.async.commit_group;\n"); }
__device__ __forceinline__ void cpw1() { asm volatile("cp.async.wait_group 1;\n"); }
__device__ __forceinline__ void gdwait() {
    asm volatile("griddepcontrol.wait;" ::: "memory");
}
__device__ __forceinline__ void gdlaunch() {
    asm volatile("griddepcontrol.launch_dependents;" ::: "memory");
}
__device__ __forceinline__ float sigm(float x)   { return 1.f / (1.f + __expf(-x)); }
__device__ __forceinline__ float tanhf_(float x) { return 2.f * sigm(2.f * x) - 1.f; }

__device__ __forceinline__ void ldm4(uint32_t* r, uint32_t a) {
    asm volatile("ldmatrix.sync.aligned.m8n8.x4.shared.b16 {%0,%1,%2,%3}, [%4];"
        : "=r"(r[0]), "=r"(r[1]), "=r"(r[2]), "=r"(r[3]) : "r"(a));
}
__device__ __forceinline__ uint32_t relu2(uint32_t v) {
    uint32_t r; asm("max.f16x2 %0, %1, %2;" : "=r"(r) : "r"(v), "r"(0u)); return r;
}
__device__ __forceinline__ void mma16(float* d, const uint32_t* a, uint32_t b0, uint32_t b1) {
    asm volatile("mma.sync.aligned.m16n8k16.row.col.f32.f16.f16.f32 "
        "{%0,%1,%2,%3},{%4,%5,%6,%7},{%8,%9},{%0,%1,%2,%3};"
        : "+f"(d[0]), "+f"(d[1]), "+f"(d[2]), "+f"(d[3])
        : "r"(a[0]), "r"(a[1]), "r"(a[2]), "r"(a[3]), "r"(b0), "r"(b1));
}

// modes
#define M_GATE0 0
#define M_GATE1 1
#define M_STORE 2
#define M_XGALL 4
#define M_OUT   5

// ---- GEMM core: BM=128, BN=96, 8 warps (4x2), BK=64 halves, 3-stage, occ 2 ----
#define BSTRb 12288     // 96*128 bytes per B stage
#define SMEMB (3 * (128 * 128 + BSTRb))   // 86016

template<int BM, int MODE, int NK, bool ZG, bool RELU_A>
__device__ __forceinline__ void gcore(
    int m0, int n0,
    const __half* __restrict__ A, int lda,
    const __half* __restrict__ Bw, int ldb,
    const float* __restrict__ biasg,
    const float* __restrict__ gh, const float* __restrict__ bhh,
    const float* __restrict__ hsrc, float* __restrict__ hdst, __half* __restrict__ hdstf,
    float* __restrict__ C, float* __restrict__ dout, int dstep)
{
    constexpr int ASTR = BM * 128;
    extern __shared__ float sm[];
    const uint32_t sAb = (uint32_t)__cvta_generic_to_shared(sm);
    const uint32_t sBb = sAb + 3 * ASTR;

    const int tid = threadIdx.x, lane = tid & 31, warp = tid >> 5;
    const int warpM = warp & 3, warpN = warp >> 2;     // 4 x 2
    const int lane4 = lane >> 2, lq = lane & 3;

    float acc[2][6][4];
#pragma unroll
    for (int i = 0; i < 2; i++)
#pragma unroll
        for (int j = 0; j < 6; j++)
#pragma unroll
            for (int q = 0; q < 4; q++) acc[i][j][q] = 0.f;

    auto loadA = [&](int st, int k0) {
#pragma unroll
        for (int v = tid; v < BM * 8; v += NTH) {
            int r = v >> 3, vc = v & 7;
            cp16(sAb + st * ASTR + r * 128 + ((vc ^ (r & 7)) << 4),
                 A + (size_t)(m0 + r) * lda + k0 + vc * 8);
        }
    };
    auto loadB = [&](int st, int k0) {
#pragma unroll
        for (int v = tid; v < 96 * 8; v += NTH) {
            int r = v >> 3, vc = v & 7;
            cp16(sBb + st * BSTRb + r * 128 + ((vc ^ (r & 7)) << 4),
                 Bw + (size_t)(n0 + r) * ldb + k0 + vc * 8);
        }
    };

    // B (weights) for stages 0..2 has NO dependency on the predecessor kernel:
    // issue before griddepcontrol.wait so it overlaps the predecessor's drain.
    loadB(0, 0);
    loadB(1, 64);
    loadB(2, 128);
    gdwait();                       // predecessor results now visible
    loadA(0, 0);  cpc();            // G0 = {B0,B1,B2,A0}
    loadA(1, 64); cpc();            // G1 = {A1}

    const int subrow = lane & 7;
    uint32_t aBase[2]; int r7A[2];
#pragma unroll
    for (int i = 0; i < 2; i++) {
        int row = warpM * 32 + i * 16 + subrow + ((lane >> 3) & 1) * 8;
        aBase[i] = sAb + row * 128; r7A[i] = row & 7;
    }
    uint32_t bBase[3]; int r7B[3];
#pragma unroll
    for (int jj = 0; jj < 3; jj++) {
        int row = warpN * 48 + jj * 16 + subrow + (lane >> 4) * 8;
        bBase[jj] = sBb + row * 128; r7B[jj] = row & 7;
    }
    const int kvA = lane >> 4;
    const int kvB = (lane >> 3) & 1;

    for (int kt = 0; kt < NK; kt++) {
        cpw1();                      // all groups except newest complete -> stage kt ready
        __syncthreads();
        if (kt + 2 < NK) {
            int st = (kt + 2) % 3, k0 = (kt + 2) * 64;
            if (kt + 2 >= 3) loadB(st, k0);   // stages 0..2 B pre-issued
            loadA(st, k0);
        }
        cpc();                       // unconditional: keeps group<->stage invariant

        const int st = kt % 3;
#pragma unroll
        for (int ks = 0; ks < 4; ks++) {
            uint32_t aF[2][4], bF[3][4];
#pragma unroll
            for (int i = 0; i < 2; i++) {
                ldm4(aF[i], aBase[i] + st * ASTR + (((2 * ks + kvA) ^ r7A[i]) << 4));
                if (RELU_A) {
#pragma unroll
                    for (int q = 0; q < 4; q++) aF[i][q] = relu2(aF[i][q]);
                }
            }
#pragma unroll
            for (int jj = 0; jj < 3; jj++)
                ldm4(bF[jj], bBase[jj] + st * BSTRb + (((2 * ks + kvB) ^ r7B[jj]) << 4));
#pragma unroll
            for (int j = 0; j < 6; j++)
#pragma unroll
                for (int i = 0; i < 2; i++)
                    mma16(acc[i][j], aF[i],
                          bF[j >> 1][(j & 1) * 2], bF[j >> 1][(j & 1) * 2 + 1]);
        }
    }
    __syncthreads();

    // ---------------- epilogues ----------------
    if (MODE == M_STORE || MODE == M_XGALL) {
#pragma unroll
        for (int i = 0; i < 2; i++) {
            int rr = m0 + warpM * 32 + i * 16 + lane4;
#pragma unroll
            for (int j = 0; j < 6; j++) {
                int cc = n0 + warpN * 48 + j * 8 + lq * 2;
#pragma unroll
                for (int q = 0; q < 4; q++) {
                    int r2 = rr + (q >> 1) * 8, c2 = cc + (q & 1);
                    float v = acc[i][j][q] + biasg[c2];
                    if (MODE == M_STORE) {
                        C[(size_t)r2 * GG + c2] = v;
                    } else {
                        int b = r2 / TT, t = r2 % TT;
                        C[((size_t)t * BATCH + b) * GG + c2] = v;
                    }
                }
            }
        }
        if (MODE == M_XGALL) {
            // fold: compute h0[0] (t=0 gate, h_prev=0) for rows with t==0.
            __syncthreads();
#pragma unroll
            for (int i = 0; i < 2; i++) {
                int rl = warpM * 32 + i * 16 + lane4;
#pragma unroll
                for (int j = 0; j < 6; j++) {
                    int cl = warpN * 48 + j * 8 + lq * 2;
                    *(float2*)&sm[rl * SEPIL + cl]       = make_float2(acc[i][j][0], acc[i][j][1]);
                    *(float2*)&sm[(rl + 8) * SEPIL + cl] = make_float2(acc[i][j][2], acc[i][j][3]);
                }
            }
            __syncthreads();
            const int jbase = n0 / 3;
            for (int idx = tid; idx < BM * 32; idx += NTH) {
                int bl = idx >> 5, jj = idx & 31;
                int rr = m0 + bl;
                if (rr % TT != 0) continue;
                int b = rr / TT;
                int cg = n0 + 3 * jj;
                float xr = sm[bl * SEPIL + 3 * jj + 0] + g_bih0p[cg];
                float xz = sm[bl * SEPIL + 3 * jj + 1] + g_bih0p[cg + 1];
                float xn = sm[bl * SEPIL + 3 * jj + 2] + g_bih0p[cg + 2];
                float r = sigm(xr + g_bhh0p[cg]);
                float z = sigm(xz + g_bhh0p[cg + 1]);
                float n = tanhf_(xn + r * g_bhh0p[cg + 2]);
                float hv = (1.f - z) * n;
                g_h0[0][(size_t)b * HH + jbase + jj] = hv;
                g_h0f[0][(size_t)b * HH + jbase + jj] = __float2half_rn(hv);
            }
        }
    } else if (MODE == M_OUT) {
#pragma unroll
        for (int i = 0; i < 2; i++) {
            int rr = m0 + warpM * 32 + i * 16 + lane4;
#pragma unroll
            for (int j = 0; j < 6; j++) {
                int cc = n0 + warpN * 48 + j * 8 + lq * 2;
#pragma unroll
                for (int q = 0; q < 4; q++) {
                    int r2 = rr + (q >> 1) * 8, c2 = cc + (q & 1);
                    if (c2 < YY) {
                        float v = acc[i][j][q] + biasg[c2] + g_xlast[(size_t)r2 * YY + c2];
                        dout[((size_t)r2 * DS + dstep) * YY + c2] = v;
                        g_xlast[(size_t)r2 * YY + c2] = v;
                        g_xlastf[(size_t)r2 * KPAD + c2] = __float2half_rn(v);
                    }
                }
            }
        }
    } else {  // M_GATE0 / M_GATE1: acc -> smem -> fused gate math
#pragma unroll
        for (int i = 0; i < 2; i++) {
            int rl = warpM * 32 + i * 16 + lane4;
#pragma unroll
            for (int j = 0; j < 6; j++) {
                int cl = warpN * 48 + j * 8 + lq * 2;
                *(float2*)&sm[rl * SEPIL + cl]       = make_float2(acc[i][j][0], acc[i][j][1]);
                *(float2*)&sm[(rl + 8) * SEPIL + cl] = make_float2(acc[i][j][2], acc[i][j][3]);
            }
        }
        __syncthreads();
        const int jbase = n0 / 3;
        for (int idx = tid; idx < BM * 32; idx += NTH) {
            int bl = idx >> 5, jj = idx & 31;
            int b = m0 + bl;
            int cg = n0 + 3 * jj;
            float ar = sm[bl * SEPIL + 3 * jj + 0];
            float az = sm[bl * SEPIL + 3 * jj + 1];
            float an = sm[bl * SEPIL + 3 * jj + 2];
            float xr, xz, xn, gr, gz, gn, hp;
            if (MODE == M_GATE0) {
                const float* xg = gh + (size_t)b * GG;   // x-side pre-stored WITH bias
                xr = xg[cg]; xz = xg[cg + 1]; xn = xg[cg + 2];
                gr = ar + bhh[cg]; gz = az + bhh[cg + 1]; gn = an + bhh[cg + 2];
                hp = hsrc[(size_t)b * HH + jbase + jj];
            } else {
                xr = ar + biasg[cg]; xz = az + biasg[cg + 1]; xn = an + biasg[cg + 2];
                if (ZG) {
                    gr = bhh[cg]; gz = bhh[cg + 1]; gn = bhh[cg + 2]; hp = 0.f;
                } else {
                    const float* g = gh + (size_t)b * GG;
                    gr = g[cg]; gz = g[cg + 1]; gn = g[cg + 2];
                    hp = hsrc[(size_t)b * HH + jbase + jj];
                }
            }
            float r = sigm(xr + gr), z = sigm(xz + gz);
            float nn_ = tanhf_(xn + r * gn);
            float hv = (1.f - z) * nn_ + z * hp;
            hdst[(size_t)b * HH + jbase + jj] = hv;
            hdstf[(size_t)b * HH + jbase + jj] = __float2half_rn(hv);
        }
    }
}

// h1 buffer index: t=0 lives in dedicated buffer 2 (avoids parity alias with t=12)
__device__ __forceinline__ int h1idx(int t) { return (t == 0) ? 2 : (t & 1); }

// ---------------- wavefront phase kernel ----------------
// roles: 0=G0(t=p)  1=X1(t=p-1)  2=G1(t=p-2)  3=XGN(xg0_new)
//        4=OUT(dstep=d-1)  5=GATE0INIT(decode d+1)
// per-p z->role: p=1:{0,1,4(d>0)}  p=2:{0,1,3(d>0)}  p=3..12:{0,1,2}
//                p=13:{1,2}  p=14:{2,5(d<12)}
// grid (16, 8, nz): BM=128 m-tiles, BN=96 n-tiles
__global__ void __launch_bounds__(NTH, 2) k_phase(int d, int p,
                                                  float* __restrict__ dout,
                                                  const float* __restrict__ bout) {
    int m0 = blockIdx.y * 128, n0 = blockIdx.x * 96;
    int z = blockIdx.z;
    int role;
    if (p == 1)       role = (z == 2) ? 4 : z;
    else if (p == 2)  role = (z == 2) ? 3 : z;
    else if (p <= 12) role = z;
    else if (p == 13) role = z + 1;
    else              role = (z == 0) ? 2 : 5;

    if (role == 0) {
        int t = p;
        int slot = (d + t) % TT;
        gcore<128, M_GATE0, 8, false, false>(m0, n0,
            g_h0f[(t - 1) & 1], HH, g_Whh0h, HH, nullptr,
            g_xg0 + (size_t)slot * BATCH * GG, g_bhh0p,
            g_h0[(t - 1) & 1], g_h0[t & 1], g_h0f[t & 1],
            nullptr, nullptr, 0);
    } else if (role == 1) {
        int t = p - 1;
        if (t == 0)
            gcore<128, M_GATE1, 8, true, false>(m0, n0,
                g_h0f[0], HH, g_Wih1h, HH, g_bih1p,
                nullptr, g_bhh1p,
                nullptr, g_h1[2], g_h1f[2], nullptr, nullptr, 0);
        else
            gcore<128, M_STORE, 8, false, false>(m0, n0,
                g_h0f[t & 1], HH, g_Wih1h, HH, g_bih1p,
                nullptr, nullptr, nullptr, nullptr, nullptr,
                g_xg1r[t & 1], nullptr, 0);
    } else if (role == 2) {
        int t = p - 2;
        int pidx = h1idx(t - 1);
        gcore<128, M_GATE0, 8, false, false>(m0, n0,
            g_h1f[pidx], HH, g_Whh1h, HH, nullptr,
            g_xg1r[t & 1], g_bhh1p,
            g_h1[pidx], g_h1[t & 1], g_h1f[t & 1],
            nullptr, nullptr, 0);
    } else if (role == 3) {
        int slot = (d + 12) % TT;   // == (d-1) % TT for d >= 1
        gcore<128, M_STORE, 3, false, false>(m0, n0,
            g_xlastf, KPAD, g_Wih0h, KPAD, g_bih0p,
            nullptr, nullptr, nullptr, nullptr, nullptr,
            g_xg0 + (size_t)slot * BATCH * GG, nullptr, 0);
    } else if (role == 4) {
        if (blockIdx.x < 2)
            gcore<128, M_OUT, 8, false, true>(m0, n0,
                g_h1f[0], HH, g_Wouth, HH, bout, nullptr, nullptr,
                nullptr, nullptr, nullptr, nullptr, dout, d - 1);
    } else {  // role 5: gate0 init for decode d+1 (h_prev = 0)
        gdwait();
        const float* ring = g_xg0 + (size_t)((d + 1) % TT) * BATCH * GG;
        int base = (blockIdx.y * gridDim.x + blockIdx.x) * NTH + threadIdx.x;
        int stride = gridDim.x * gridDim.y * NTH;
        for (int idx = base; idx < BATCH * HH; idx += stride) {
            int b = idx >> 9, j = idx & 511;
            const float* xg = ring + (size_t)b * GG;
            int c = 3 * j;
            float r = sigm(xg[c] + g_bhh0p[c]);
            float zz = sigm(xg[c + 1] + g_bhh0p[c + 1]);
            float n = tanhf_(xg[c + 2] + r * g_bhh0p[c + 2]);
            float hv = (1.f - zz) * n;
            g_h0[0][idx] = hv;
            g_h0f[0][idx] = __float2half_rn(hv);
        }
    }
    gdlaunch();
}

// final output GEMM for dstep = 12 (grid (2,8))
__global__ void __launch_bounds__(NTH, 2) k_fout(float* __restrict__ dout,
                                                 const float* __restrict__ bout) {
    gcore<128, M_OUT, 8, false, true>(blockIdx.y * 128, blockIdx.x * 96,
        g_h1f[0], HH, g_Wouth, HH, bout, nullptr, nullptr,
        nullptr, nullptr, nullptr, nullptr, dout, DS - 1);
    gdlaunch();
}

__global__ void __launch_bounds__(NTH, 2) k_xg0_all() {
    gcore<128, M_XGALL, 3, false, false>(blockIdx.y * 128, blockIdx.x * 96,
        g_xpf, KPAD, g_Wih0h, KPAD, g_bih0p,
        nullptr, nullptr, nullptr, nullptr, nullptr, g_xg0, nullptr, 0);
}

__global__ void k_init(const float* __restrict__ x) {
    int idx = blockIdx.x * blockDim.x + threadIdx.x;
    if (idx < BATCH * TT * KPAD) {
        int row = idx / KPAD, k = idx % KPAD;
        g_xpf[idx] = (k < YY) ? __float2half_rn(x[(size_t)row * YY + k]) : __float2half_rn(0.f);
    }
    if (idx < BATCH * KPAD) {
        int b = idx / KPAD, k = idx % KPAD;
        if (k < YY) {
            float v = x[((size_t)b * TT + (TT - 1)) * YY + k];
            g_xlast[(size_t)b * YY + k] = v;
            g_xlastf[idx] = __float2half_rn(v);
        } else {
            g_xlastf[idx] = __float2half_rn(0.f);
        }
    }
}

__global__ void k_prep(const float* __restrict__ Wih0, const float* __restrict__ Whh0,
                       const float* __restrict__ bih0, const float* __restrict__ bhh0,
                       const float* __restrict__ Wih1, const float* __restrict__ Whh1,
                       const float* __restrict__ bih1, const float* __restrict__ bhh1,
                       const float* __restrict__ Wout) {
    int i = blockIdx.x * blockDim.x + threadIdx.x;
    if (i < GG * HH) {
        int c = i / HH, k = i % HH;
        int pr = (c % 3) * HH + c / 3;
        g_Whh0h[i] = __float2half_rn(Whh0[(size_t)pr * HH + k]);
        g_Wih1h[i] = __float2half_rn(Wih1[(size_t)pr * HH + k]);
        g_Whh1h[i] = __float2half_rn(Whh1[(size_t)pr * HH + k]);
    }
    if (i < GG * KPAD) {
        int c = i / KPAD, k = i % KPAD;
        int pr = (c % 3) * HH + c / 3;
        g_Wih0h[i] = (k < YY) ? __float2half_rn(Wih0[(size_t)pr * YY + k]) : __float2half_rn(0.f);
    }
    if (i < KPAD * HH) {
        int r = i / HH, k = i % HH;
        g_Wouth[i] = (r < YY) ? __float2half_rn(Wout[(size_t)r * HH + k]) : __float2half_rn(0.f);
    }
    if (i < GG) {
        int pr = (i % 3) * HH + i / 3;
        g_bih0p[i] = bih0[pr];
        g_bhh0p[i] = bhh0[pr];
        g_bih1p[i] = bih1[pr];
        g_bhh1p[i] = bhh1[pr];
    }
}

// ---------------- host ----------------
static void launch_pdl(const void* func, dim3 grid, dim3 block, size_t smem, void** args) {
    cudaLaunchConfig_t cfg = {};
    cfg.gridDim = grid;
    cfg.blockDim = block;
    cfg.dynamicSmemBytes = smem;
    cudaLaunchAttribute attr[1];
    attr[0].id = cudaLaunchAttributeProgrammaticStreamSerialization;
    attr[0].val.programmaticStreamSerializationAllowed = 1;
    cfg.attrs = attr;
    cfg.numAttrs = 1;
    cfg.stream = 0;
    cudaLaunchKernelExC(&cfg, func, args);
}

extern "C" void kernel_launch(void* const* d_in, const int* in_sizes, int n_in,
                              void* d_out, int out_size) {
    (void)in_sizes; (void)n_in; (void)out_size;
    const float* x    = (const float*)d_in[0];
    const float* Wih0 = (const float*)d_in[1];
    const float* Whh0 = (const float*)d_in[2];
    const float* bih0 = (const float*)d_in[3];
    const float* bhh0 = (const float*)d_in[4];
    const float* Wih1 = (const float*)d_in[5];
    const float* Whh1 = (const float*)d_in[6];
    const float* bih1 = (const float*)d_in[7];
    const float* bhh1 = (const float*)d_in[8];
    const float* Wout = (const float*)d_in[9];
    const float* bout = (const float*)d_in[10];
    float* dout = (float*)d_out;

    cudaFuncSetAttribute(k_phase,   cudaFuncAttributeMaxDynamicSharedMemorySize, SMEMB);
    cudaFuncSetAttribute(k_fout,    cudaFuncAttributeMaxDynamicSharedMemorySize, SMEMB);
    cudaFuncSetAttribute(k_xg0_all, cudaFuncAttributeMaxDynamicSharedMemorySize, SMEMB);

    k_prep<<<(GG * HH + 255) / 256, 256>>>(Wih0, Whh0, bih0, bhh0,
                                           Wih1, Whh1, bih1, bhh1, Wout);
    k_init<<<(BATCH * TT * KPAD + 255) / 256, 256>>>(x);
    k_xg0_all<<<dim3(16, BATCH * TT / 128), NTH, SMEMB>>>();   // also seeds h0[0]

    for (int d = 0; d < DS; d++) {
        for (int p = 1; p <= 14; p++) {
            int nz;
            if (p == 1)       nz = (d > 0) ? 3 : 2;
            else if (p == 2)  nz = (d > 0) ? 3 : 2;
            else if (p <= 12) nz = 3;
            else if (p == 13) nz = 2;
            else              nz = (d + 1 < DS) ? 2 : 1;
            void* args[] = { &d, &p, &dout, &bout };
            launch_pdl((const void*)&k_phase, dim3(16, 8, nz), dim3(NTH), SMEMB, args);
        }
    }
    {
        void* args[] = { &dout, &bout };
        launch_pdl((const void*)&k_fout, dim3(2, 8), dim3(NTH), SMEMB, args);
    }
}